// round 11
// baseline (speedup 1.0000x reference)
#include <cuda_runtime.h>
#include <cuda_fp16.h>

#define BB    16
#define NN    65536
#define CC    256
#define DINN  16
#define DOUTT 16

__device__ __align__(16) float  g_sf[DINN * BB * CC];     // s: [i][b][k], fp32
__device__ __align__(16) float  g_wdt[CC * DOUTT * DINN]; // w_diag: [c][o][i]
__device__ __align__(16) float  g_off[BB * CC * DOUTT];   // off: [b][c][o]
__device__ unsigned char g_chunk[NN];                     // chunk id per row n

__device__ __forceinline__ float4 shfl_xor_f4(float4 v, int m) {
    v.x = __shfl_xor_sync(0xffffffffu, v.x, m);
    v.y = __shfl_xor_sync(0xffffffffu, v.y, m);
    v.z = __shfl_xor_sync(0xffffffffu, v.z, m);
    v.w = __shfl_xor_sync(0xffffffffu, v.w, m);
    return v;
}
__device__ __forceinline__ float dot4(float4 a, float4 b) {
    return a.x*b.x + a.y*b.y + a.z*b.z + a.w*b.w;
}
__device__ __forceinline__ void mma16816(float& d0, float& d1, float& d2, float& d3,
                                         unsigned a0, unsigned a1, unsigned a2, unsigned a3,
                                         unsigned b0, unsigned b1) {
    asm volatile(
        "mma.sync.aligned.m16n8k16.row.col.f32.f16.f16.f32 "
        "{%0,%1,%2,%3}, {%4,%5,%6,%7}, {%8,%9}, {%0,%1,%2,%3};\n"
        : "+f"(d0), "+f"(d1), "+f"(d2), "+f"(d3)
        : "r"(a0), "r"(a1), "r"(a2), "r"(a3), "r"(b0), "r"(b1));
}

// ---------------------------------------------------------------------------
// kT: transpose w_diag [o][i][c] -> [c][o*16+i]; zero g_sf; build chunk map.
// ---------------------------------------------------------------------------
__global__ __launch_bounds__(256) void kT(const float* __restrict__ wdiag,
                                          const int* __restrict__ pid) {
    int idx = blockIdx.x * 256 + threadIdx.x;      // 65536 total
    int c  = idx & 255;
    int oi = idx >> 8;
    g_wdt[c * 256 + oi] = wdiag[idx];
    g_sf[idx] = 0.f;
    g_chunk[pid[idx]] = (unsigned char)(idx >> 8);
}

// ---------------------------------------------------------------------------
// kA (streaming): s[i][b][chunk[n]] += x[b][n][i], x read LINEARLY.
// grid (32, 16): block = 2048 rows of batch b. smem accumulator [ch][i],
// stride 17 for bank spread; flush via spread fp32 REDG into g_sf.
// ---------------------------------------------------------------------------
__global__ __launch_bounds__(256) void kA(const float* __restrict__ x) {
    int b = blockIdx.y;
    int t = threadIdx.x;
    __shared__ float sloc[256 * 17];               // 17.4 KB

#pragma unroll
    for (int j = t; j < 256 * 17; j += 256) sloc[j] = 0.f;
    __syncthreads();

    int base = blockIdx.x * 2048;                  // row base
    const float4* xb = (const float4*)(x + ((size_t)b * NN + base) * DINN);

    // 2048 rows * 4 float4 = 8192 float4 / 256 thr = 32 passes, unrolled by 4
#pragma unroll 1
    for (int pp = 0; pp < 32; pp += 4) {
        float4 v[4];
        int ch[4], q4[4];
#pragma unroll
        for (int u = 0; u < 4; u++) {
            int f = (pp + u) * 256 + t;
            v[u]  = __ldg(xb + f);
            int n = base + (f >> 2);
            ch[u] = __ldg(&g_chunk[n]);
            q4[u] = (f & 3) * 4;
        }
#pragma unroll
        for (int u = 0; u < 4; u++) {
            float* sp = sloc + ch[u] * 17 + q4[u];
            atomicAdd(sp + 0, v[u].x);
            atomicAdd(sp + 1, v[u].y);
            atomicAdd(sp + 2, v[u].z);
            atomicAdd(sp + 3, v[u].w);
        }
    }
    __syncthreads();

    // flush: thread t owns chunk t; 17-stride reads are conflict-free (17 coprime 32)
    int c = t;
#pragma unroll
    for (int i = 0; i < 16; i++) {
        float val = sloc[c * 17 + i];
        atomicAdd(&g_sf[((size_t)i * BB + b) * CC + c], val);
    }
}

// ---------------------------------------------------------------------------
// kB (tensor-core): per c, D[16b][16o] = sum_kappa s[b][kappa]*w_off[kappa][o]
// Identical to R10 except s staged from fp32 g_sf with on-the-fly half2 cvt.
// ---------------------------------------------------------------------------
__global__ __launch_bounds__(256) void kB(const float* __restrict__ woff) {
    int c    = blockIdx.x;
    int t    = threadIdx.x;
    int w    = t >> 5;
    int lane = t & 31;
    int r    = lane >> 2;
    int cp   = (lane & 3) * 2;
    int W    = w * 32;

    __shared__ __align__(16) __half sh_s[16 * 256];
    __shared__ __align__(16) __half sh_w[16 * 256];
    __shared__ __align__(16) float  dred[8 * 256];

    int so[4], sk4[4];
#pragma unroll
    for (int rr = 0; rr < 4; rr++) {
        int F = t + 256 * rr;
        so[rr]  = F >> 6;
        sk4[rr] = F & 63;
    }

    float4 wbuf[4];
    float4 f0, f1, f2, f3;
    const float4* gsf4 = (const float4*)g_sf;      // slice i = 1024 float4

    // preload slice 0
#pragma unroll
    for (int rr = 0; rr < 4; rr++)
        wbuf[rr] = __ldg((const float4*)(woff + (((size_t)so[rr] * 16 + 0) * CC + c) * CC) + sk4[rr]);
    f0 = gsf4[2 * t];
    f1 = gsf4[2 * t + 1];
    f2 = gsf4[2 * t + 512];
    f3 = gsf4[2 * t + 513];

    float d0[4] = {0.f, 0.f, 0.f, 0.f};
    float d1[4] = {0.f, 0.f, 0.f, 0.f};

    for (int i = 0; i < 16; i++) {
        // store staged slice i (fp32 -> half2)
#pragma unroll
        for (int rr = 0; rr < 4; rr++) {
            __half2 h0 = __floats2half2_rn(wbuf[rr].x, wbuf[rr].y);
            __half2 h1 = __floats2half2_rn(wbuf[rr].z, wbuf[rr].w);
            *(uint2*)&sh_w[so[rr] * 256 + sk4[rr] * 4] =
                make_uint2(*(unsigned*)&h0, *(unsigned*)&h1);
        }
        {
            __half2 a0 = __floats2half2_rn(f0.x, f0.y), a1 = __floats2half2_rn(f0.z, f0.w);
            __half2 a2 = __floats2half2_rn(f1.x, f1.y), a3 = __floats2half2_rn(f1.z, f1.w);
            ((uint4*)sh_s)[t] = make_uint4(*(unsigned*)&a0, *(unsigned*)&a1,
                                           *(unsigned*)&a2, *(unsigned*)&a3);
            __half2 b0 = __floats2half2_rn(f2.x, f2.y), b1 = __floats2half2_rn(f2.z, f2.w);
            __half2 b2 = __floats2half2_rn(f3.x, f3.y), b3 = __floats2half2_rn(f3.z, f3.w);
            ((uint4*)sh_s)[t + 256] = make_uint4(*(unsigned*)&b0, *(unsigned*)&b1,
                                                 *(unsigned*)&b2, *(unsigned*)&b3);
        }
        __syncthreads();

        // prefetch slice i+1
        if (i < 15) {
#pragma unroll
            for (int rr = 0; rr < 4; rr++)
                wbuf[rr] = __ldg((const float4*)(woff + (((size_t)so[rr] * 16 + (i + 1)) * CC + c) * CC) + sk4[rr]);
            int sb = (i + 1) * 1024;
            f0 = gsf4[sb + 2 * t];
            f1 = gsf4[sb + 2 * t + 1];
            f2 = gsf4[sb + 2 * t + 512];
            f3 = gsf4[sb + 2 * t + 513];
        }

#pragma unroll
        for (int ks = 0; ks < 2; ks++) {
            int kb = W + ks * 16 + cp;
            unsigned a0 = *(const unsigned*)&sh_s[r * 256 + kb];
            unsigned a1 = *(const unsigned*)&sh_s[(r + 8) * 256 + kb];
            unsigned a2 = *(const unsigned*)&sh_s[r * 256 + kb + 8];
            unsigned a3 = *(const unsigned*)&sh_s[(r + 8) * 256 + kb + 8];
            unsigned b00 = *(const unsigned*)&sh_w[r * 256 + kb];
            unsigned b01 = *(const unsigned*)&sh_w[r * 256 + kb + 8];
            unsigned b10 = *(const unsigned*)&sh_w[(8 + r) * 256 + kb];
            unsigned b11 = *(const unsigned*)&sh_w[(8 + r) * 256 + kb + 8];
            mma16816(d0[0], d0[1], d0[2], d0[3], a0, a1, a2, a3, b00, b01);
            mma16816(d1[0], d1[1], d1[2], d1[3], a0, a1, a2, a3, b10, b11);
        }
        __syncthreads();
    }

    *(float2*)&dred[w * 256 + r * 16 + cp]            = make_float2(d0[0], d0[1]);
    *(float2*)&dred[w * 256 + (r + 8) * 16 + cp]      = make_float2(d0[2], d0[3]);
    *(float2*)&dred[w * 256 + r * 16 + 8 + cp]        = make_float2(d1[0], d1[1]);
    *(float2*)&dred[w * 256 + (r + 8) * 16 + 8 + cp]  = make_float2(d1[2], d1[3]);
    __syncthreads();

    float sum = 0.f;
#pragma unroll
    for (int ww = 0; ww < 8; ww++) sum += dred[ww * 256 + t];
    int b = t >> 4, o = t & 15;
    g_off[((size_t)b * CC + c) * DOUTT + o] = sum * (1.0f / (float)NN);
}

// ---------------------------------------------------------------------------
// kC (R6 exact, measured best ~32us)
// ---------------------------------------------------------------------------
__global__ __launch_bounds__(256, 3) void kC(const float* __restrict__ x,
                                             const int* __restrict__ pid,
                                             const float* __restrict__ b1,
                                             float* __restrict__ out) {
    int c = blockIdx.x, b = blockIdx.y;
    int t = threadIdx.x;
    int q = t & 3, g = t >> 2;

    const int* pc = pid + c * 256;
    int ns[4];
    ns[0] = __ldg(pc + g);
    ns[1] = __ldg(pc + g + 64);
    ns[2] = __ldg(pc + g + 128);
    ns[3] = __ldg(pc + g + 192);

    float4 wreg[4][4];
    float  bs[4];
    const float* wc = g_wdt + c * 256;
#pragma unroll
    for (int oo = 0; oo < 4; oo++) {
        int o = 4 * q + oo;
        bs[oo] = __ldg(&g_off[((size_t)b * CC + c) * DOUTT + o]) + __ldg(b1 + o);
#pragma unroll
        for (int p = 0; p < 4; p++)
            wreg[oo][p] = *(const float4*)(wc + o * 16 + 4 * (q ^ p));
    }

    const float* xb = x + (size_t)b * NN * DINN;
    float* ob = out + (size_t)b * NN * DOUTT;

#pragma unroll
    for (int j = 0; j < 4; j++) {
        int n = ns[j];
        float4 X0 = ((const float4*)(xb + (size_t)n * DINN))[q];
        float4 X1 = shfl_xor_f4(X0, 1);
        float4 X2 = shfl_xor_f4(X0, 2);
        float4 X3 = shfl_xor_f4(X0, 3);

        float r0 = bs[0], r1 = bs[1], r2 = bs[2], r3 = bs[3];
        r0 += dot4(wreg[0][0], X0) + dot4(wreg[0][1], X1) + dot4(wreg[0][2], X2) + dot4(wreg[0][3], X3);
        r1 += dot4(wreg[1][0], X0) + dot4(wreg[1][1], X1) + dot4(wreg[1][2], X2) + dot4(wreg[1][3], X3);
        r2 += dot4(wreg[2][0], X0) + dot4(wreg[2][1], X1) + dot4(wreg[2][2], X2) + dot4(wreg[2][3], X3);
        r3 += dot4(wreg[3][0], X0) + dot4(wreg[3][1], X1) + dot4(wreg[3][2], X2) + dot4(wreg[3][3], X3);

        ((float4*)(ob + (size_t)n * DOUTT))[q] = make_float4(r0, r1, r2, r3);
    }
}

extern "C" void kernel_launch(void* const* d_in, const int* in_sizes, int n_in,
                              void* d_out, int out_size) {
    const float* x     = (const float*)d_in[0];
    const float* wdiag = (const float*)d_in[1];
    const float* woff  = (const float*)d_in[2];
    const float* b1    = (const float*)d_in[3];
    const int*   pid   = (const int*)d_in[4];
    float* out = (float*)d_out;

    kT<<<256, 256>>>(wdiag, pid);
    kA<<<dim3(32, BB), 256>>>(x);
    kB<<<CC, 256>>>(woff);
    kC<<<dim3(CC, BB), 256>>>(x, pid, b1, out);
}